// round 1
// baseline (speedup 1.0000x reference)
#include <cuda_runtime.h>
#include <cstdint>

#define BB 1024
#define TT 128
#define KK 128
#define START_TAG 126
#define STOP_TAG  127

// Scratch: partition history rows 0..last_idx-1 per batch (64 MB), pointers, lengths.
__device__ float g_part[(size_t)BB * TT * KK];
__device__ int   g_ptr[BB];
__device__ int   g_li[BB];

#define NEG_INF __int_as_float(0xff800000)

__global__ __launch_bounds__(128, 3)
void viterbi_fwd(const float* __restrict__ feats,
                 const float* __restrict__ trans,
                 const void*  __restrict__ masks,
                 float* __restrict__ out)
{
    extern __shared__ float tr[];            // KK*KK floats (64 KB)
    __shared__ float buf[2][KK];
    __shared__ float red_v[4];
    __shared__ int   red_i[4];

    const int b   = blockIdx.x;
    const int tid = threadIdx.x;             // = cur tag, also = t for mask read

    // Stage transitions into shared memory (float4 strided).
    {
        const float4* t4 = (const float4*)trans;
        float4* s4 = (float4*)tr;
        #pragma unroll
        for (int i = tid; i < KK * KK / 4; i += 128) s4[i] = t4[i];
    }

    // Mask dtype sniff: lengths >= 64 so masks[0][1..3] are true.
    // uint8 layout -> bytes 1..3 nonzero; int32 layout (value 1) -> bytes 1..3 zero.
    const unsigned char* mu = (const unsigned char*)masks;
    const bool isU8 = (mu[1] | mu[2] | mu[3]) != 0;
    bool mb;
    if (isU8) mb = mu[(size_t)b * TT + tid] != 0;
    else      mb = ((const int*)masks)[(size_t)b * TT + tid] != 0;
    const int length = __syncthreads_count(mb);   // also fences the trans load
    const int li = length - 1;                    // last valid index, in [63,127]

    // t = 0 init: partition[cur] = feats[b,0,cur] + trans[START,cur]
    float myp = feats[((size_t)b * TT) * KK + tid] + tr[START_TAG * KK + tid];
    buf[0][tid] = myp;
    __syncthreads();

    const int cur = tid;
    for (int t = 1; t <= li; ++t) {
        const float* oldp = buf[(t - 1) & 1];
        float*       newp = buf[t & 1];

        // Spill previous partition row (needed by backward argmax recompute).
        g_part[((size_t)b * TT + (t - 1)) * KK + tid] = myp;

        float b0 = NEG_INF, b1 = NEG_INF, b2 = NEG_INF, b3 = NEG_INF;
        const float4* o4 = (const float4*)oldp;
        #pragma unroll 8
        for (int q = 0; q < KK / 4; ++q) {
            const float4 pv = o4[q];               // broadcast LDS.128
            const int pr = q * 4;
            b0 = fmaxf(b0, pv.x + tr[(pr + 0) * KK + cur]);
            b1 = fmaxf(b1, pv.y + tr[(pr + 1) * KK + cur]);
            b2 = fmaxf(b2, pv.z + tr[(pr + 2) * KK + cur]);
            b3 = fmaxf(b3, pv.w + tr[(pr + 3) * KK + cur]);
        }
        float best = fmaxf(fmaxf(b0, b1), fmaxf(b2, b3));
        myp = best + feats[((size_t)b * TT + t) * KK + cur];
        newp[tid] = myp;
        __syncthreads();
    }

    // STOP transition: val[prev] = partition_li[prev] + trans[prev][STOP]
    // Block argmax with first-index tie-break (matches jnp.argmax).
    {
        float v   = myp + tr[tid * KK + STOP_TAG];   // thread = prev
        int   idx = tid;
        #pragma unroll
        for (int off = 16; off > 0; off >>= 1) {
            float ov = __shfl_xor_sync(0xffffffffu, v, off);
            int   oi = __shfl_xor_sync(0xffffffffu, idx, off);
            if (ov > v || (ov == v && oi < idx)) { v = ov; idx = oi; }
        }
        const int warp = tid >> 5;
        if ((tid & 31) == 0) { red_v[warp] = v; red_i[warp] = idx; }
        __syncthreads();
        if (tid == 0) {
            float bv = red_v[0]; int bi = red_i[0];
            #pragma unroll
            for (int w = 1; w < 4; ++w) {
                if (red_v[w] > bv || (red_v[w] == bv && red_i[w] < bi)) {
                    bv = red_v[w]; bi = red_i[w];
                }
            }
            out[b]   = bv;    // path_score
            g_ptr[b] = bi;    // pointer (best last tag)
            g_li[b]  = li;
        }
    }
}

// One warp per batch: serial backtrace, recomputing each backpointer as a
// 128-wide argmax over (part_hist[j][prev] + trans[prev][ptr]).
__global__ __launch_bounds__(256)
void viterbi_bwd(const float* __restrict__ trans,
                 float* __restrict__ out)
{
    const int gw   = (blockIdx.x * blockDim.x + threadIdx.x) >> 5;
    const int lane = threadIdx.x & 31;
    if (gw >= BB) return;
    const int b = gw;

    const int pointer = g_ptr[b];
    const int li      = g_li[b];
    int ptr = pointer;

    float* dec = out + BB + (size_t)b * TT;
    if (lane == 0) dec[TT - 1] = (float)pointer;

    for (int j = TT - 2; j >= 0; --j) {
        if (j > li) {
            ptr = 0;                       // masked bp rows are zero
        } else if (j == li) {
            ptr = pointer;                 // bp_all[last_idx] overwritten with pointer
        } else {
            const float* row = &g_part[((size_t)b * TT + j) * KK];
            const float4 pv = ((const float4*)row)[lane];
            const int base = lane * 4;
            float c0 = pv.x + trans[(base + 0) * KK + ptr];
            float c1 = pv.y + trans[(base + 1) * KK + ptr];
            float c2 = pv.z + trans[(base + 2) * KK + ptr];
            float c3 = pv.w + trans[(base + 3) * KK + ptr];
            float v = c0; int idx = base;
            if (c1 > v) { v = c1; idx = base + 1; }
            if (c2 > v) { v = c2; idx = base + 2; }
            if (c3 > v) { v = c3; idx = base + 3; }
            #pragma unroll
            for (int off = 16; off > 0; off >>= 1) {
                float ov = __shfl_xor_sync(0xffffffffu, v, off);
                int   oi = __shfl_xor_sync(0xffffffffu, idx, off);
                if (ov > v || (ov == v && oi < idx)) { v = ov; idx = oi; }
            }
            ptr = idx;                     // converged on all lanes
        }
        if (lane == 0) dec[j] = (float)ptr;
    }
}

extern "C" void kernel_launch(void* const* d_in, const int* in_sizes, int n_in,
                              void* d_out, int out_size)
{
    const float* feats = (const float*)d_in[0];
    const float* trans = (const float*)d_in[1];
    const void*  masks = d_in[2];
    float* out = (float*)d_out;

    static bool attr_done = false;
    if (!attr_done) {
        cudaFuncSetAttribute(viterbi_fwd,
                             cudaFuncAttributeMaxDynamicSharedMemorySize,
                             KK * KK * (int)sizeof(float));
        attr_done = true;
    }

    viterbi_fwd<<<BB, 128, KK * KK * sizeof(float)>>>(feats, trans, masks, out);
    viterbi_bwd<<<BB * 32 / 256, 256>>>(trans, out);
}

// round 2
// speedup vs baseline: 1.5257x; 1.5257x over previous
#include <cuda_runtime.h>
#include <cstdint>

#define BB 1024
#define TT 128
#define KK 128
#define START_TAG 126
#define STOP_TAG  127
#define NEG_INF __int_as_float(0xff800000)

// Scratch: partition history (64 MB) + transposed transitions.
__device__ float g_part[(size_t)BB * TT * KK];
__device__ float g_trT[KK * KK];

__global__ void transpose_trans(const float* __restrict__ trans) {
    int idx = blockIdx.x * blockDim.x + threadIdx.x;   // 0..16383
    int p = idx >> 7, c = idx & 127;
    g_trT[c * KK + p] = trans[idx];
}

__device__ __forceinline__ unsigned sortable(float f) {
    unsigned u = __float_as_uint(f);
    return u ^ ((unsigned)((int)u >> 31) | 0x80000000u);
}

__global__ __launch_bounds__(256, 2)
void viterbi_fused(const float* __restrict__ feats,
                   const float* __restrict__ trans,
                   const void*  __restrict__ masks,
                   float* __restrict__ out)
{
    extern __shared__ float strT[];          // KK*KK floats (64 KB), backtrace phase
    __shared__ float pbuf[2][KK];
    __shared__ float partial[2][KK];
    __shared__ float s_rv[4];
    __shared__ int   s_ri[4];
    __shared__ int   s_ptr;

    const int b   = blockIdx.x;
    const int tid = threadIdx.x;
    const int h   = tid >> 7;                // prev-half: h*64 .. h*64+63
    const int c   = tid & 127;               // cur tag

    // Transition column segment -> registers (read once, reused every step).
    float trc[64];
    #pragma unroll
    for (int j = 0; j < 64; ++j)
        trc[j] = trans[(h * 64 + j) * KK + c];   // coalesced across c

    // Mask dtype sniff (lengths >= 64 so masks[0][1..3] true if uint8 layout).
    const unsigned char* mu = (const unsigned char*)masks;
    const bool isU8 = (mu[1] | mu[2] | mu[3]) != 0;
    bool mb = false;
    if (tid < TT)
        mb = isU8 ? (mu[(size_t)b * TT + tid] != 0)
                  : (((const int*)masks)[(size_t)b * TT + tid] != 0);
    const int li = __syncthreads_count(mb) - 1;   // last valid index, in [63,127]

    const float* fb = feats + (size_t)b * TT * KK;

    // t = 0 init: partition[c] = feats[b,0,c] + trans[START,c].
    // START=126 lives in half 1's registers (trc[62]). Half 0 prefetches feat t=1.
    float fq = 0.f;
    if (h == 0) fq = fb[1 * KK + c];
    else        pbuf[0][c] = fb[c] + trc[START_TAG - 64];
    __syncthreads();

    for (int t = 1; t <= li; ++t) {
        float fnext = 0.f, spillv = 0.f;
        const int tn = (t < li) ? t + 1 : li;
        if (h == 0) fnext = fb[tn * KK + c];          // prefetch next feat
        else        spillv = pbuf[(t - 1) & 1][c];    // old row for history spill

        const float4* o4 = (const float4*)(pbuf[(t - 1) & 1]) + h * 16;
        float a0 = NEG_INF, a1 = NEG_INF, a2 = NEG_INF, a3 = NEG_INF;
        #pragma unroll
        for (int q = 0; q < 16; ++q) {
            const float4 pv = o4[q];                  // broadcast LDS.128
            a0 = fmaxf(a0, pv.x + trc[4 * q + 0]);
            a1 = fmaxf(a1, pv.y + trc[4 * q + 1]);
            a2 = fmaxf(a2, pv.z + trc[4 * q + 2]);
            a3 = fmaxf(a3, pv.w + trc[4 * q + 3]);
        }
        partial[h][c] = fmaxf(fmaxf(a0, a1), fmaxf(a2, a3));
        if (h == 1)
            g_part[((size_t)b * TT + (t - 1)) * KK + c] = spillv;
        __syncthreads();
        if (h == 0) {
            pbuf[t & 1][c] = fmaxf(partial[0][c], partial[1][c]) + fq;
            fq = fnext;
        }
        __syncthreads();
    }

    // Stage transposed transitions into smem for the backtrace.
    {
        const float4* src = (const float4*)g_trT;
        float4* dst = (float4*)strT;
        #pragma unroll
        for (int i = tid; i < KK * KK / 4; i += 256)
            dst[i] = src[i];
    }

    // STOP transition argmax over prev (first-index tie-break, matches jnp.argmax).
    if (tid < KK) {
        float v = pbuf[li & 1][tid] + g_trT[STOP_TAG * KK + tid];
        unsigned s = sortable(v);
        unsigned smax = __reduce_max_sync(0xffffffffu, s);
        unsigned m = __ballot_sync(0xffffffffu, s == smax);
        int leader = __ffs(m) - 1;
        int lane = tid & 31, w = tid >> 5;
        if (lane == leader) { s_rv[w] = v; s_ri[w] = tid; }
    }
    __syncthreads();
    if (tid == 0) {
        float bv = s_rv[0]; int bi = s_ri[0];
        #pragma unroll
        for (int w = 1; w < 4; ++w)
            if (s_rv[w] > bv || (s_rv[w] == bv && s_ri[w] < bi)) { bv = s_rv[w]; bi = s_ri[w]; }
        out[b] = bv;      // path_score
        s_ptr = bi;       // best last tag
    }
    __syncthreads();

    // Backtrace: warp 0 only. Recompute each backpointer as a 128-wide argmax
    // over part_hist[j][prev] + trT[ptr][prev]. g_part rows prefetched 2 deep
    // (addresses don't depend on ptr); trT from smem (29-cyc LDS).
    if (tid < 32) {
        const int lane = tid;
        const int pointer = s_ptr;
        int ptr = pointer;
        float* dec = out + BB + (size_t)b * TT;
        if (lane == 0) dec[TT - 1] = (float)pointer;

        const float4* prow = (const float4*)(g_part + (size_t)b * TT * KK);
        float4 r_j   = prow[((TT - 2) * KK) >> 2 | 0] ;  // placeholder overwritten below
        r_j          = prow[(((TT - 2) * KK) >> 2) + lane];
        float4 r_jm1 = prow[(((TT - 3) * KK) >> 2) + lane];

        for (int j = TT - 2; j >= 0; --j) {
            int jp = j - 2; if (jp < 0) jp = 0;
            float4 r_new = prow[((jp * KK) >> 2) + lane];   // prefetch row j-2

            if (j > li) {
                ptr = 0;                        // masked bp rows are zero
            } else if (j == li) {
                ptr = pointer;                  // bp_all[last_idx] := pointer
            } else {
                const float4 tv = *(const float4*)(strT + ptr * KK + 4 * lane);
                float c0 = r_j.x + tv.x;
                float c1 = r_j.y + tv.y;
                float c2 = r_j.z + tv.z;
                float c3 = r_j.w + tv.w;
                const int base = lane * 4;
                float v = c0; int idx = base;
                if (c1 > v) { v = c1; idx = base + 1; }
                if (c2 > v) { v = c2; idx = base + 2; }
                if (c3 > v) { v = c3; idx = base + 3; }
                unsigned s = sortable(v);
                unsigned smax = __reduce_max_sync(0xffffffffu, s);
                unsigned mm = __ballot_sync(0xffffffffu, s == smax);
                int leader = __ffs(mm) - 1;     // lowest lane = lowest prev (tie-break)
                ptr = __shfl_sync(0xffffffffu, idx, leader);
            }
            if (lane == 0) dec[j] = (float)ptr;
            r_j = r_jm1; r_jm1 = r_new;
        }
    }
}

extern "C" void kernel_launch(void* const* d_in, const int* in_sizes, int n_in,
                              void* d_out, int out_size)
{
    const float* feats = (const float*)d_in[0];
    const float* trans = (const float*)d_in[1];
    const void*  masks = d_in[2];
    float* out = (float*)d_out;

    static bool attr_done = false;
    if (!attr_done) {
        cudaFuncSetAttribute(viterbi_fused,
                             cudaFuncAttributeMaxDynamicSharedMemorySize,
                             KK * KK * (int)sizeof(float));
        attr_done = true;
    }

    transpose_trans<<<KK * KK / 256, 256>>>(trans);
    viterbi_fused<<<BB, 256, KK * KK * sizeof(float)>>>(feats, trans, masks, out);
}